// round 13
// baseline (speedup 1.0000x reference)
#include <cuda_runtime.h>
#include <cuda_bf16.h>
#include <cuda_fp16.h>
#include <cstdint>

// ===========================================================================
// Problem constants
// ===========================================================================
#define B_    2
#define L_    1024
#define P_    1024
#define T_    2048
#define HID_  2048
#define NH_   32
#define NKV_  8
#define D_    64
#define SCALE_ 0.125f
#define QKVW  3072
#define WSCALE 32.0f
#define WSCALE_INV 0.03125f

// ===========================================================================
// PTX helpers
// ===========================================================================
__device__ __forceinline__ uint32_t smem_to_u32(const void* smem_ptr) {
    uint32_t addr;
    asm("{ .reg .u64 tmp; cvta.to.shared.u64 tmp, %1; cvt.u32.u64 %0, tmp; }"
        : "=r"(addr) : "l"(smem_ptr));
    return addr;
}

__device__ __forceinline__ void ldsm_x4(uint32_t (&r)[4], uint32_t addr) {
    asm volatile("ldmatrix.sync.aligned.m8n8.x4.shared.b16 {%0,%1,%2,%3}, [%4];"
        : "=r"(r[0]), "=r"(r[1]), "=r"(r[2]), "=r"(r[3]) : "r"(addr));
}

// bf16 mma (attention)
__device__ __forceinline__ void mma_bf16(float (&d)[4], const uint32_t (&a)[4],
                                         uint32_t b0, uint32_t b1) {
    asm volatile(
        "mma.sync.aligned.m16n8k16.row.col.f32.bf16.bf16.f32 "
        "{%0,%1,%2,%3}, {%4,%5,%6,%7}, {%8,%9}, {%0,%1,%2,%3};"
        : "+f"(d[0]), "+f"(d[1]), "+f"(d[2]), "+f"(d[3])
        : "r"(a[0]), "r"(a[1]), "r"(a[2]), "r"(a[3]), "r"(b0), "r"(b1));
}

// fp16 mma (projection GEMMs)
__device__ __forceinline__ void mma_fp16(float (&d)[4], const uint32_t (&a)[4],
                                         uint32_t b0, uint32_t b1) {
    asm volatile(
        "mma.sync.aligned.m16n8k16.row.col.f32.f16.f16.f32 "
        "{%0,%1,%2,%3}, {%4,%5,%6,%7}, {%8,%9}, {%0,%1,%2,%3};"
        : "+f"(d[0]), "+f"(d[1]), "+f"(d[2]), "+f"(d[3])
        : "r"(a[0]), "r"(a[1]), "r"(a[2]), "r"(a[3]), "r"(b0), "r"(b1));
}

__device__ __forceinline__ void cp_async16(uint32_t saddr, const void* gaddr) {
    asm volatile("cp.async.cg.shared.global [%0], [%1], 16;"
        :: "r"(saddr), "l"(gaddr));
}
#define CP_COMMIT() asm volatile("cp.async.commit_group;" ::: "memory")
#define CP_WAIT2()  asm volatile("cp.async.wait_group 2;" ::: "memory")
#define CP_WAIT1()  asm volatile("cp.async.wait_group 1;" ::: "memory")
#define CP_WAIT0()  asm volatile("cp.async.wait_group 0;" ::: "memory")

// ===========================================================================
// Scratch
// ===========================================================================
__device__ float g_qkvlin[B_ * L_ * QKVW];

__device__ __half g_xh [B_ * L_ * HID_];               // fp16 hi of x
__device__ __half g_ath[B_ * L_ * NH_ * D_];           // attention out (fp16 hi)
__device__ __half g_wcat_h[QKVW * HID_];               // fp16 of 32*W (K-major)
__device__ __half g_wcat_l[QKVW * HID_];               // fp16 residual of 32*W
__device__ __half g_wot_h[HID_ * (NH_ * D_)];
__device__ __half g_wot_l[HID_ * (NH_ * D_)];
__device__ float  g_bcat[QKVW];

// attention operands (split bf16, unchanged numerics)
__device__ __nv_bfloat16 g_qh [B_ * NH_ * L_ * D_];
__device__ __nv_bfloat16 g_ql [B_ * NH_ * L_ * D_];
__device__ __nv_bfloat16 g_kh [B_ * NKV_ * T_ * D_];
__device__ __nv_bfloat16 g_kl [B_ * NKV_ * T_ * D_];
__device__ __nv_bfloat16 g_vth[B_ * NKV_ * D_ * T_];
__device__ __nv_bfloat16 g_vtl[B_ * NKV_ * D_ * T_];

__device__ __forceinline__ void split_bf16(float a, __nv_bfloat16& hi, __nv_bfloat16& lo)
{
    hi = __float2bfloat16_rn(a);
    lo = __float2bfloat16_rn(a - __bfloat162float(hi));
}

__device__ __forceinline__ void pack2_split(float x, float y, uint32_t& uh, uint32_t& ul)
{
    __nv_bfloat162 hb = __floats2bfloat162_rn(x, y);
    float lx = x - __bfloat162float(hb.x);
    float ly = y - __bfloat162float(hb.y);
    __nv_bfloat162 lb = __floats2bfloat162_rn(lx, ly);
    uh = *(uint32_t*)&hb;
    ul = *(uint32_t*)&lb;
}

// ===========================================================================
// Merged prep kernel. Flat grid 14348 blocks, 256 threads:
//  [0,4096)      Wq -> wcat rows [0,2048)      (fp16 pair, x32 scaled)
//  [4096,5120)   Wk -> wcat rows [2048,2560)
//  [5120,6144)   Wv -> wcat rows [2560,3072)
//  [6144,10240)  Wo -> wot
//  [10240,14336) x  -> fp16 hi
//  [14336,14348) bias concat
// ===========================================================================
__device__ __forceinline__ void transpose_seg_h(
    const float* __restrict__ W, __half* __restrict__ Th,
    __half* __restrict__ Tl, int K, int N, int n0, int k0,
    int tx, int ty, float (*t)[33])
{
#pragma unroll
    for (int i = 0; i < 4; i++)
        t[ty + 8 * i][tx] = W[(size_t)(k0 + ty + 8 * i) * N + n0 + tx];
    __syncthreads();
#pragma unroll
    for (int i = 0; i < 4; i++) {
        float a = t[tx][ty + 8 * i] * WSCALE;
        __half h = __float2half_rn(a);
        __half l = __float2half_rn(a - __half2float(h));
        size_t o = (size_t)(n0 + ty + 8 * i) * K + k0 + tx;
        Th[o] = h;
        Tl[o] = l;
    }
}

__global__ void prep_w_kernel(
    const float* __restrict__ Wq, const float* __restrict__ Wk,
    const float* __restrict__ Wv, const float* __restrict__ Wo,
    const float* __restrict__ bq, const float* __restrict__ bk,
    const float* __restrict__ bv, const float* __restrict__ x,
    __half* __restrict__ wch, __half* __restrict__ wcl,
    __half* __restrict__ woh, __half* __restrict__ wol,
    float* __restrict__ bcat, __half* __restrict__ xh)
{
    __shared__ float t[32][33];
    const int bid = blockIdx.x;
    const int tid = threadIdx.x;
    const int tx = tid & 31, ty = tid >> 5;

    if (bid < 4096) {
        int lb = bid;
        transpose_seg_h(Wq, wch, wcl, HID_, 2048,
                        (lb & 63) * 32, (lb >> 6) * 32, tx, ty, t);
    } else if (bid < 5120) {
        int lb = bid - 4096;
        transpose_seg_h(Wk, wch + (size_t)2048 * HID_, wcl + (size_t)2048 * HID_,
                        HID_, 512, (lb & 15) * 32, (lb >> 4) * 32, tx, ty, t);
    } else if (bid < 6144) {
        int lb = bid - 5120;
        transpose_seg_h(Wv, wch + (size_t)2560 * HID_, wcl + (size_t)2560 * HID_,
                        HID_, 512, (lb & 15) * 32, (lb >> 4) * 32, tx, ty, t);
    } else if (bid < 10240) {
        int lb = bid - 6144;
        transpose_seg_h(Wo, woh, wol, NH_ * D_, HID_,
                        (lb & 63) * 32, (lb >> 6) * 32, tx, ty, t);
    } else if (bid < 14336) {
        int i = ((bid - 10240) * 256 + tid) * 4;
        float4 v = *(const float4*)(x + i);
        *(__half2*)(xh + i)     = __floats2half2_rn(v.x, v.y);
        *(__half2*)(xh + i + 2) = __floats2half2_rn(v.z, v.w);
    } else {
        int i = (bid - 14336) * 256 + tid;
        if (i < QKVW)
            bcat[i] = (i < 2048) ? bq[i] : (i < 2560) ? bk[i - 2048] : bv[i - 2560];
    }
}

// ===========================================================================
// 2-term fp16 mma.sync GEMM: C[M,N] = (A_hi[M,K] @ (Bh+Bl)[N,K]^T)/32 (+ bias)
// 128x128 CTA, K-chunk 32, 3-stage pipeline, 3 tiles/stage (Ah, Bh, Bl).
// 8 warps: warp tile 32(M) x 64(N). Target 2 CTAs/SM.
// ===========================================================================
#define SROW_B   80
#define TILE_2T  (128 * SROW_B)             // 10240
#define STAGE_2T (3 * TILE_2T)              // 30720
#define GEMM2T_SMEM (3 * STAGE_2T)          // 92160

__global__ __launch_bounds__(256, 2) void gemm_2t_kernel(
    const __half* __restrict__ A,
    const __half* __restrict__ Bh, const __half* __restrict__ Bl,
    const float* __restrict__ bias, float* __restrict__ C, int N, int K)
{
    extern __shared__ char smem[];
    const uint32_t sb = smem_to_u32(smem);
    const int tid = threadIdx.x;
    const int lid = tid & 31;
    const int wid = tid >> 5;
    const int wm = wid & 3;
    const int wn = wid >> 2;
    const int bn = blockIdx.x * 128;
    const int bm = blockIdx.y * 128;

    const int arow = (lid & 7) + ((lid >> 3) & 1) * 8;
    const int akof = (lid >> 4) * 8;
    const int brow = (lid & 7) + (lid >> 4) * 8;
    const int bkof = ((lid >> 3) & 1) * 8;

    float acc[2][8][4];
#pragma unroll
    for (int mi = 0; mi < 2; mi++)
#pragma unroll
        for (int ni = 0; ni < 8; ni++)
#pragma unroll
            for (int u = 0; u < 4; u++) acc[mi][ni][u] = 0.f;

    const int nch = K >> 5;

    auto issue_stage = [&](int ch, int stg) {
        const uint32_t db = sb + (uint32_t)(stg * STAGE_2T);
        const int k0 = ch << 5;
#pragma unroll
        for (int i = 0; i < 6; i++) {
            int idx = tid + i * 256;          // 0..1535
            int tile = idx >> 9;              // 0:A 1:Bh 2:Bl
            int sub = idx & 511;
            int r = sub >> 2, c = sub & 3;
            const __half* g = (tile == 0) ? A : (tile == 1) ? Bh : Bl;
            int rowbase = (tile == 0) ? bm : bn;
            cp_async16(db + (uint32_t)(tile * TILE_2T + r * SROW_B + c * 16),
                       g + (size_t)(rowbase + r) * K + k0 + c * 8);
        }
        CP_COMMIT();
    };

    issue_stage(0, 0);
    if (nch > 1) issue_stage(1, 1);

    for (int ch = 0; ch < nch; ch++) {
        if (ch + 2 < nch) { issue_stage(ch + 2, (ch + 2) % 3); CP_WAIT2(); }
        else if (ch + 1 < nch) { CP_WAIT1(); }
        else { CP_WAIT0(); }
        __syncthreads();

        const uint32_t ub  = sb + (uint32_t)((ch % 3) * STAGE_2T);
        const uint32_t uA  = ub;
        const uint32_t uBh = ub + TILE_2T;
        const uint32_t uBl = ub + 2 * TILE_2T;

#pragma unroll
        for (int ks = 0; ks < 2; ks++) {
            uint32_t ahf[2][4], bhf[4][4], blf[4][4];
#pragma unroll
            for (int mi = 0; mi < 2; mi++) {
                uint32_t ao = (uint32_t)((wm * 32 + mi * 16 + arow) * SROW_B +
                                         (ks * 16 + akof) * 2);
                ldsm_x4(ahf[mi], uA + ao);
            }
#pragma unroll
            for (int pr = 0; pr < 4; pr++) {
                uint32_t bo = (uint32_t)((wn * 64 + pr * 16 + brow) * SROW_B +
                                         (ks * 16 + bkof) * 2);
                ldsm_x4(bhf[pr], uBh + bo);
                ldsm_x4(blf[pr], uBl + bo);
            }
#pragma unroll
            for (int mi = 0; mi < 2; mi++)
#pragma unroll
                for (int ni = 0; ni < 8; ni++) {
                    int pr = ni >> 1, s = (ni & 1) * 2;
                    mma_fp16(acc[mi][ni], ahf[mi], bhf[pr][s], bhf[pr][s + 1]);
                    mma_fp16(acc[mi][ni], ahf[mi], blf[pr][s], blf[pr][s + 1]);
                }
        }
        __syncthreads();
    }

#pragma unroll
    for (int mi = 0; mi < 2; mi++) {
        int r0 = bm + wm * 32 + mi * 16 + (lid >> 2);
#pragma unroll
        for (int ni = 0; ni < 8; ni++) {
            int col = bn + wn * 64 + ni * 8 + (lid & 3) * 2;
            float b0 = 0.f, b1 = 0.f;
            if (bias) { b0 = bias[col]; b1 = bias[col + 1]; }
            float2 v0 = make_float2(acc[mi][ni][0] * WSCALE_INV + b0,
                                    acc[mi][ni][1] * WSCALE_INV + b1);
            float2 v1 = make_float2(acc[mi][ni][2] * WSCALE_INV + b0,
                                    acc[mi][ni][3] * WSCALE_INV + b1);
            *(float2*)(C + (size_t)r0 * N + col)       = v0;
            *(float2*)(C + (size_t)(r0 + 8) * N + col) = v1;
        }
    }
}

// ===========================================================================
// Merged scatter from fused QKV output (unchanged bf16-split outputs)
// ===========================================================================
__global__ void scatter_qkv_kernel(
    const float* __restrict__ qkv,
    const float* __restrict__ cosb, const float* __restrict__ sinb,
    __nv_bfloat16* __restrict__ qh, __nv_bfloat16* __restrict__ ql,
    __nv_bfloat16* __restrict__ kh, __nv_bfloat16* __restrict__ kl,
    __nv_bfloat16* __restrict__ vth, __nv_bfloat16* __restrict__ vtl)
{
    __shared__ float t[32][33];
    const int bid = blockIdx.x;
    const int tid = threadIdx.x;

    if (bid < 16384) {
        int idx = bid * 256 + tid;
        int d = idx & 63;
        int h = (idx >> 6) & 31;
        int l = (idx >> 11) & 1023;
        int b = idx >> 21;
        size_t rb = (size_t)(b * L_ + l) * QKVW + h * 64;
        float v  = qkv[rb + d];
        int  d2  = (d < 32) ? d + 32 : d - 32;
        float vp = qkv[rb + d2];
        float rot = (d < 32) ? -vp : vp;
        float o = v * cosb[l * 64 + d] + rot * sinb[l * 64 + d];
        __nv_bfloat16 hi, lo;
        split_bf16(o, hi, lo);
        size_t dst = (((size_t)(b * NH_ + h)) * L_ + l) * D_ + d;
        qh[dst] = hi;
        ql[dst] = lo;
    } else if (bid < 20480) {
        int idx = (bid - 16384) * 256 + tid;
        int d = idx & 63;
        int h = (idx >> 6) & 7;
        int l = (idx >> 9) & 1023;
        int b = idx >> 19;
        size_t rb = (size_t)(b * L_ + l) * QKVW + 2048 + h * 64;
        float v  = qkv[rb + d];
        int  d2  = (d < 32) ? d + 32 : d - 32;
        float vp = qkv[rb + d2];
        float rot = (d < 32) ? -vp : vp;
        float o = v * cosb[l * 64 + d] + rot * sinb[l * 64 + d];
        __nv_bfloat16 hi, lo;
        split_bf16(o, hi, lo);
        size_t dst = (((size_t)(b * NKV_ + h)) * T_ + (P_ + l)) * D_ + d;
        kh[dst] = hi;
        kl[dst] = lo;
    } else {
        int lb = bid - 20480;
        int d0 = (lb & 1) * 32;
        int l0 = ((lb >> 1) & 31) * 32;
        int bh = lb >> 6;
        int b = bh >> 3, h = bh & 7;
        int tx = tid & 31, ty = tid >> 5;
#pragma unroll
        for (int i = 0; i < 4; i++)
            t[ty + 8 * i][tx] =
                qkv[(size_t)(b * L_ + l0 + ty + 8 * i) * QKVW + 2560 + h * 64 + d0 + tx];
        __syncthreads();
#pragma unroll
        for (int i = 0; i < 4; i++) {
            float a = t[tx][ty + 8 * i];
            __nv_bfloat16 hi, lo;
            split_bf16(a, hi, lo);
            size_t dst = (((size_t)(b * NKV_ + h)) * D_ + d0 + ty + 8 * i) * T_ +
                         P_ + l0 + tx;
            vth[dst] = hi;
            vtl[dst] = lo;
        }
    }
}

// ===========================================================================
// Merged past-KV processing (unchanged)
// ===========================================================================
__global__ void scatter_past_kernel(
    const float* __restrict__ pk, const float* __restrict__ pv,
    __nv_bfloat16* __restrict__ kh, __nv_bfloat16* __restrict__ kl,
    __nv_bfloat16* __restrict__ vth, __nv_bfloat16* __restrict__ vtl)
{
    __shared__ float t[32][33];
    const int bid = blockIdx.x;
    const int tid = threadIdx.x;

    if (bid < 4096) {
        int idx = bid * 256 + tid;
        int d = idx & 63;
        int tt = (idx >> 6) & 1023;
        int h = (idx >> 16) & 7;
        int b = idx >> 19;
        __nv_bfloat16 hi, lo;
        split_bf16(pk[idx], hi, lo);
        size_t dst = (((size_t)(b * NKV_ + h)) * T_ + tt) * D_ + d;
        kh[dst] = hi;
        kl[dst] = lo;
    } else {
        int lb = bid - 4096;
        int d0 = (lb & 1) * 32;
        int l0 = ((lb >> 1) & 31) * 32;
        int bh = lb >> 6;
        int tx = tid & 31, ty = tid >> 5;
#pragma unroll
        for (int i = 0; i < 4; i++)
            t[ty + 8 * i][tx] =
                pv[((size_t)bh * P_ + l0 + ty + 8 * i) * D_ + d0 + tx];
        __syncthreads();
#pragma unroll
        for (int i = 0; i < 4; i++) {
            float a = t[tx][ty + 8 * i];
            __nv_bfloat16 hi, lo;
            split_bf16(a, hi, lo);
            size_t dst = ((size_t)bh * D_ + d0 + ty + 8 * i) * T_ + l0 + tx;
            vth[dst] = hi;
            vtl[dst] = lo;
        }
    }
}

// ===========================================================================
// Tensor-core flash attention (bf16 3-term, unchanged numerics).
// Output now written as fp16 hi only (feeds the 2-term O-proj).
// ===========================================================================
#define VROW   72
#define QT_B   (128 * VROW * 2)
#define KT_B   (64 * VROW * 2)
#define KVBUF  (4 * KT_B)
#define ATTN_SMEM (2 * QT_B + 2 * KVBUF)

__global__ __launch_bounds__(256) void attn_mma_kernel(
    const __nv_bfloat16* __restrict__ Qh, const __nv_bfloat16* __restrict__ Ql,
    const __nv_bfloat16* __restrict__ Kh, const __nv_bfloat16* __restrict__ Kl,
    const __nv_bfloat16* __restrict__ Vth, const __nv_bfloat16* __restrict__ Vtl,
    __half* __restrict__ Oh)
{
    extern __shared__ char smem[];
    const uint32_t sb = smem_to_u32(smem);
    const uint32_t sQh = sb;
    const uint32_t sQl = sb + QT_B;
    const uint32_t sKV = sb + 2 * QT_B;

    const int tid = threadIdx.x;
    const int lid = tid & 31;
    const int wid = tid >> 5;
    const int qb  = (L_ / 128 - 1) - blockIdx.x;
    const int h   = blockIdx.y;
    const int b   = blockIdx.z;
    const int hk  = h >> 2;
    const int q0  = qb * 128;
    const int ntiles = (P_ + q0 + 128) / 64;

    const int arow = (lid & 7) + ((lid >> 3) & 1) * 8;
    const int akof = (lid >> 4) * 8;
    const int brow = (lid & 7) + (lid >> 4) * 8;
    const int bkof = ((lid >> 3) & 1) * 8;

    const __nv_bfloat16* qh_base = Qh + ((size_t)(b * NH_ + h) * L_ + q0) * D_;
    const __nv_bfloat16* ql_base = Ql + ((size_t)(b * NH_ + h) * L_ + q0) * D_;
    const __nv_bfloat16* kh_base = Kh + (size_t)(b * NKV_ + hk) * T_ * D_;
    const __nv_bfloat16* kl_base = Kl + (size_t)(b * NKV_ + hk) * T_ * D_;
    const __nv_bfloat16* vh_base = Vth + (size_t)(b * NKV_ + hk) * D_ * T_;
    const __nv_bfloat16* vl_base = Vtl + (size_t)(b * NKV_ + hk) * D_ * T_;

    const int ltile = tid >> 6;
    const int lsub  = tid & 63;
    const __nv_bfloat16* kvg =
        (ltile == 0) ? kh_base : (ltile == 1) ? kl_base :
        (ltile == 2) ? vh_base : vl_base;
    const bool isV = (ltile >= 2);
    const uint32_t kvs_off = (uint32_t)(ltile * KT_B);

    {
        const uint32_t db = sKV + kvs_off;
#pragma unroll
        for (int i = 0; i < 8; i++) {
            int chunk = lsub + i * 64;
            int r = chunk >> 3, c = chunk & 7;
            const __nv_bfloat16* src = isV
                ? kvg + (size_t)r * T_ + c * 8
                : kvg + (size_t)r * D_ + c * 8;
            cp_async16(db + (uint32_t)(r * 144 + c * 16), src);
        }
        CP_COMMIT();
    }

#pragma unroll
    for (int t = 0; t < 2; t++) {
        const __nv_bfloat16* src = t ? ql_base : qh_base;
        const uint32_t dstb = t ? sQl : sQh;
#pragma unroll
        for (int i = 0; i < 4; i++) {
            int chunk = tid + i * 256;
            int r = chunk >> 3, c = chunk & 7;
            uint4 v = *(const uint4*)(src + (size_t)r * D_ + c * 8);
            *(uint4*)(smem + (dstb - sb) + r * 144 + c * 16) = v;
        }
    }

    float o[8][4];
#pragma unroll
    for (int ni = 0; ni < 8; ni++)
#pragma unroll
        for (int u = 0; u < 4; u++) o[ni][u] = 0.f;
    float m1 = -1e30f, m2 = -1e30f, l1 = 0.f, l2 = 0.f;

    const int qi1 = q0 + wid * 16 + (lid >> 2);
    const int qi2 = qi1 + 8;
    const int lim1 = qi1 + P_;
    const int lim2 = qi2 + P_;

    for (int kt = 0; kt < ntiles; kt++) {
        if (kt + 1 < ntiles) {
            const uint32_t db = sKV + ((kt + 1) & 1) * KVBUF + kvs_off;
            const int t0 = (kt + 1) * 64;
#pragma unroll
            for (int i = 0; i < 8; i++) {
                int chunk = lsub + i * 64;
                int r = chunk >> 3, c = chunk & 7;
                const __nv_bfloat16* src = isV
                    ? kvg + (size_t)r * T_ + t0 + c * 8
                    : kvg + (size_t)(t0 + r) * D_ + c * 8;
                cp_async16(db + (uint32_t)(r * 144 + c * 16), src);
            }
            CP_COMMIT();
            CP_WAIT1();
        } else {
            CP_WAIT0();
        }
        __syncthreads();

        const uint32_t ub  = sKV + (kt & 1) * KVBUF;
        const uint32_t uKh = ub;
        const uint32_t uKl = ub + KT_B;
        const uint32_t uVh = ub + 2 * KT_B;
        const uint32_t uVl = ub + 3 * KT_B;

        float s[8][4];
#pragma unroll
        for (int ni = 0; ni < 8; ni++)
#pragma unroll
            for (int u = 0; u < 4; u++) s[ni][u] = 0.f;

#pragma unroll
        for (int ks = 0; ks < 4; ks++) {
            uint32_t ahf[4], alf[4];
            uint32_t ao = (uint32_t)((wid * 16 + arow) * 144 + (ks * 16 + akof) * 2);
            ldsm_x4(ahf, sQh + ao);
            ldsm_x4(alf, sQl + ao);
#pragma unroll
            for (int pr = 0; pr < 4; pr++) {
                uint32_t bhf[4], blf[4];
                uint32_t bo = (uint32_t)((pr * 16 + brow) * 144 + (ks * 16 + bkof) * 2);
                ldsm_x4(bhf, uKh + bo);
                ldsm_x4(blf, uKl + bo);
#pragma unroll
                for (int t = 0; t < 2; t++) {
                    int ni = 2 * pr + t, s2 = t * 2;
                    mma_bf16(s[ni], ahf, bhf[s2], bhf[s2 + 1]);
                    mma_bf16(s[ni], ahf, blf[s2], blf[s2 + 1]);
                    mma_bf16(s[ni], alf, bhf[s2], bhf[s2 + 1]);
                }
            }
        }

#pragma unroll
        for (int ni = 0; ni < 8; ni++)
#pragma unroll
            for (int u = 0; u < 4; u++) s[ni][u] *= SCALE_;

        if (kt >= ntiles - 2) {
            int jc = kt * 64 + 2 * (lid & 3);
#pragma unroll
            for (int ni = 0; ni < 8; ni++) {
                int j = jc + 8 * ni;
                if (j     > lim1) s[ni][0] = -1e30f;
                if (j + 1 > lim1) s[ni][1] = -1e30f;
                if (j     > lim2) s[ni][2] = -1e30f;
                if (j + 1 > lim2) s[ni][3] = -1e30f;
            }
        }

        float mx1 = -1e30f, mx2 = -1e30f;
#pragma unroll
        for (int ni = 0; ni < 8; ni++) {
            mx1 = fmaxf(mx1, fmaxf(s[ni][0], s[ni][1]));
            mx2 = fmaxf(mx2, fmaxf(s[ni][2], s[ni][3]));
        }
        mx1 = fmaxf(mx1, __shfl_xor_sync(0xffffffffu, mx1, 1));
        mx1 = fmaxf(mx1, __shfl_xor_sync(0xffffffffu, mx1, 2));
        mx2 = fmaxf(mx2, __shfl_xor_sync(0xffffffffu, mx2, 1));
        mx2 = fmaxf(mx2, __shfl_xor_sync(0xffffffffu, mx2, 2));

        float mn1 = fmaxf(m1, mx1), mn2 = fmaxf(m2, mx2);
        float c1 = __expf(m1 - mn1), c2 = __expf(m2 - mn2);
        m1 = mn1; m2 = mn2;

        float p1 = 0.f, p2 = 0.f;
#pragma unroll
        for (int ni = 0; ni < 8; ni++) {
            s[ni][0] = __expf(s[ni][0] - mn1);
            s[ni][1] = __expf(s[ni][1] - mn1);
            s[ni][2] = __expf(s[ni][2] - mn2);
            s[ni][3] = __expf(s[ni][3] - mn2);
            p1 += s[ni][0] + s[ni][1];
            p2 += s[ni][2] + s[ni][3];
        }
        p1 += __shfl_xor_sync(0xffffffffu, p1, 1);
        p1 += __shfl_xor_sync(0xffffffffu, p1, 2);
        p2 += __shfl_xor_sync(0xffffffffu, p2, 1);
        p2 += __shfl_xor_sync(0xffffffffu, p2, 2);
        l1 = l1 * c1 + p1;
        l2 = l2 * c2 + p2;

#pragma unroll
        for (int ni = 0; ni < 8; ni++) {
            o[ni][0] *= c1; o[ni][1] *= c1;
            o[ni][2] *= c2; o[ni][3] *= c2;
        }

#pragma unroll
        for (int ks = 0; ks < 4; ks++) {
            uint32_t aPh[4], aPl[4];
            pack2_split(s[2 * ks][0],     s[2 * ks][1],     aPh[0], aPl[0]);
            pack2_split(s[2 * ks][2],     s[2 * ks][3],     aPh[1], aPl[1]);
            pack2_split(s[2 * ks + 1][0], s[2 * ks + 1][1], aPh[2], aPl[2]);
            pack2_split(s[2 * ks + 1][2], s[2 * ks + 1][3], aPh[3], aPl[3]);
#pragma unroll
            for (int pr = 0; pr < 4; pr++) {
                uint32_t bvh[4], bvl[4];
                uint32_t bo = (uint32_t)((pr * 16 + brow) * 144 + (ks * 16 + bkof) * 2);
                ldsm_x4(bvh, uVh + bo);
                ldsm_x4(bvl, uVl + bo);
#pragma unroll
                for (int t = 0; t < 2; t++) {
                    int ni = 2 * pr + t, s2 = t * 2;
                    mma_bf16(o[ni], aPh, bvh[s2], bvh[s2 + 1]);
                    mma_bf16(o[ni], aPh, bvl[s2], bvl[s2 + 1]);
                    mma_bf16(o[ni], aPl, bvh[s2], bvh[s2 + 1]);
                }
            }
        }
        __syncthreads();
    }

    float inv1 = 1.f / l1, inv2 = 1.f / l2;
    size_t base1 = (((size_t)b * L_ + qi1) * NH_ + h) * D_;
    size_t base2 = (((size_t)b * L_ + qi2) * NH_ + h) * D_;
#pragma unroll
    for (int ni = 0; ni < 8; ni++) {
        int d = 8 * ni + 2 * (lid & 3);
        *(__half2*)(Oh + base1 + d) = __floats2half2_rn(o[ni][0] * inv1, o[ni][1] * inv1);
        *(__half2*)(Oh + base2 + d) = __floats2half2_rn(o[ni][2] * inv2, o[ni][3] * inv2);
    }
}

// ===========================================================================
// Launch
// ===========================================================================
extern "C" void kernel_launch(void* const* d_in, const int* in_sizes, int n_in,
                              void* d_out, int out_size)
{
    const float* x      = (const float*)d_in[0];
    const float* cosb   = (const float*)d_in[2];
    const float* sinb   = (const float*)d_in[3];
    const float* past_k = (const float*)d_in[4];
    const float* past_v = (const float*)d_in[5];
    const float* Wq     = (const float*)d_in[6];
    const float* bq     = (const float*)d_in[7];
    const float* Wk     = (const float*)d_in[8];
    const float* bk     = (const float*)d_in[9];
    const float* Wv     = (const float*)d_in[10];
    const float* bv     = (const float*)d_in[11];
    const float* Wo     = (const float*)d_in[12];
    float* out          = (float*)d_out;

    float *qkvlin, *bcat;
    cudaGetSymbolAddress((void**)&qkvlin, g_qkvlin);
    cudaGetSymbolAddress((void**)&bcat,   g_bcat);

    __half *xh, *ath, *wch, *wcl, *woh, *wol;
    __nv_bfloat16 *qh, *ql, *kh, *kl, *vth, *vtl;
    cudaGetSymbolAddress((void**)&xh,  g_xh);
    cudaGetSymbolAddress((void**)&ath, g_ath);
    cudaGetSymbolAddress((void**)&wch, g_wcat_h);
    cudaGetSymbolAddress((void**)&wcl, g_wcat_l);
    cudaGetSymbolAddress((void**)&woh, g_wot_h);
    cudaGetSymbolAddress((void**)&wol, g_wot_l);
    cudaGetSymbolAddress((void**)&qh,  g_qh);
    cudaGetSymbolAddress((void**)&ql,  g_ql);
    cudaGetSymbolAddress((void**)&kh,  g_kh);
    cudaGetSymbolAddress((void**)&kl,  g_kl);
    cudaGetSymbolAddress((void**)&vth, g_vth);
    cudaGetSymbolAddress((void**)&vtl, g_vtl);

    const int M = B_ * L_;  // 2048

    cudaFuncSetAttribute(gemm_2t_kernel,
                         cudaFuncAttributeMaxDynamicSharedMemorySize, GEMM2T_SMEM);
    cudaFuncSetAttribute(attn_mma_kernel,
                         cudaFuncAttributeMaxDynamicSharedMemorySize, ATTN_SMEM);

    // 1. all weight/bias/x prep
    prep_w_kernel<<<14348, 256>>>(Wq, Wk, Wv, Wo, bq, bk, bv, x,
                                  wch, wcl, woh, wol, bcat, xh);

    // 2. past KV
    scatter_past_kernel<<<5120, 256>>>(past_k, past_v, kh, kl, vth, vtl);

    // 3. fused QKV projection (2-term fp16)
    gemm_2t_kernel<<<dim3(QKVW / 128, M / 128), 256, GEMM2T_SMEM>>>(
        xh, wch, wcl, bcat, qkvlin, QKVW, HID_);

    // 4. rope Q/K + V transpose
    scatter_qkv_kernel<<<21504, 256>>>(qkvlin, cosb, sinb,
                                       qh, ql, kh, kl, vth, vtl);

    // 5. attention (bf16 3-term)
    attn_mma_kernel<<<dim3(L_ / 128, NH_, B_), 256, ATTN_SMEM>>>(
        qh, ql, kh, kl, vth, vtl, ath);

    // 6. output projection (2-term fp16)
    gemm_2t_kernel<<<dim3(HID_ / 128, M / 128), 256, GEMM2T_SMEM>>>(
        ath, woh, wol, nullptr, out, HID_, HID_);
}